// round 12
// baseline (speedup 1.0000x reference)
#include <cuda_runtime.h>
#include <cstdint>

#define NE 8
#define DIM 1024
#define NT 256
#define F4 (DIM / 4)
#define NG 36       // lower triangle of 8x8 Gram
#define NP 64       // partials per Gram value (2-level shuffle)
#define RW 65       // NP + 1 pad (odd stride -> conflict-free)
#define NSM 152
#define GRIDSZ (NSM * 4)

__device__ __forceinline__ constexpr int tri(int i, int j) { return i * (i + 1) / 2 + j; }

__device__ __forceinline__ void cp_async16(void* smem_dst, const void* gsrc) {
    uint32_t d = (uint32_t)__cvta_generic_to_shared(smem_dst);
    asm volatile("cp.async.cg.shared.global [%0], [%1], 16;" :: "r"(d), "l"(gsrc) : "memory");
}

__global__ __launch_bounds__(NT, 4) void gram_chol_cpasync(
    const float* __restrict__ x, float* __restrict__ out, int batch) {
    const int t = threadIdx.x;
    const int warp = t >> 5;
    const int lane = t & 31;

    __shared__ float red[NG][RW];      // 9.4 KB
    __shared__ float gf_s[NG];
    __shared__ float Ls[NG];           // Cholesky; diag slots hold 1/L_jj
    __shared__ float4 buf[NE * NT];    // 32 KB prefetch buffer (next row)

    int row = blockIdx.x;
    if (row >= batch) return;

    // ---- First row: direct LDG.128 into registers ----
    float4 v[NE];
    {
        const float4* __restrict__ xin =
            reinterpret_cast<const float4*>(x + (size_t)row * NE * DIM);
#pragma unroll
        for (int i = 0; i < NE; i++) v[i] = __ldcs(&xin[i * F4 + t]);
    }

    while (true) {
        const int nrow = row + GRIDSZ;
        const bool has_next = (nrow < batch);

        // ---- Prefetch next row HBM->smem via cp.async (no register cost) ----
        if (has_next) {
            const float4* __restrict__ pin =
                reinterpret_cast<const float4*>(x + (size_t)nrow * NE * DIM);
#pragma unroll
            for (int i = 0; i < NE; i++)
                cp_async16(&buf[i * NT + t], &pin[i * F4 + t]);
        }
        asm volatile("cp.async.commit_group;");

        // ---- Gram partials: 2-level shuffle; lanes 0-7 publish 64/value ----
#pragma unroll
        for (int i = 0; i < NE; i++) {
#pragma unroll
            for (int j = 0; j <= i; j++) {
                float s = v[i].x * v[j].x + v[i].y * v[j].y +
                          v[i].z * v[j].z + v[i].w * v[j].w;
                s += __shfl_xor_sync(0xffffffffu, s, 16);
                s += __shfl_xor_sync(0xffffffffu, s, 8);
                if (lane < 8) red[tri(i, j)][warp * 8 + lane] = s;
            }
        }
        __syncthreads();

        // ---- Final reduce: threads 0..35 sum 64 partials (4-way ILP) ----
        if (t < NG) {
            float s0 = 0.f, s1 = 0.f, s2 = 0.f, s3 = 0.f;
#pragma unroll
            for (int m = 0; m < NP; m += 4) {
                s0 += red[t][m + 0];
                s1 += red[t][m + 1];
                s2 += red[t][m + 2];
                s3 += red[t][m + 3];
            }
            gf_s[t] = (s0 + s1) + (s2 + s3);
        }
        __syncthreads();

        // ---- Warp 0: lane-parallel 8x8 Cholesky ----
        if (warp == 0) {
            float grow[NE];
            const int li = lane;
#pragma unroll
            for (int k = 0; k < NE; k++) {
                const int r = (li < NE) ? li : 0;
                grow[k] = gf_s[(k <= r) ? tri(r, k) : tri(k, r)];
            }
#pragma unroll
            for (int j = 0; j < NE; j++) {
                const float diag = __shfl_sync(0xffffffffu, grow[j], j);
                const float inv = rsqrtf(diag);
                const float Lij = grow[j] * inv;
                if (li < NE && li >= j) Ls[tri(li, j)] = (li == j) ? inv : Lij;
#pragma unroll
                for (int k = 0; k < NE; k++) {
                    if (k > j) {
                        const float Lkj = __shfl_sync(0xffffffffu, Lij, k);
                        grow[k] -= Lij * Lkj;
                    }
                }
            }
        }
        __syncthreads();

        // ---- Forward substitution v <- L^-1 v, store each row as produced ----
        {
            float4* __restrict__ xout =
                reinterpret_cast<float4*>(out + (size_t)row * NE * DIM);
#pragma unroll
            for (int j = 0; j < NE; j++) {
                const float invd = Ls[tri(j, j)];
                v[j].x *= invd; v[j].y *= invd; v[j].z *= invd; v[j].w *= invd;
                __stcs(&xout[j * F4 + t], v[j]);
#pragma unroll
                for (int i = 0; i < NE; i++) {
                    if (i > j) {
                        const float lij = Ls[tri(i, j)];
                        v[i].x -= lij * v[j].x;
                        v[i].y -= lij * v[j].y;
                        v[i].z -= lij * v[j].z;
                        v[i].w -= lij * v[j].w;
                    }
                }
            }
        }

        if (!has_next) break;

        // ---- Refill v from the prefetch buffer (self-owned slots; no barrier) ----
        asm volatile("cp.async.wait_group 0;" ::: "memory");
#pragma unroll
        for (int i = 0; i < NE; i++) v[i] = buf[i * NT + t];
        row = nrow;
        __syncthreads();  // red[] reuse vs straggler warps in next publish
    }
}

extern "C" void kernel_launch(void* const* d_in, const int* in_sizes, int n_in,
                              void* d_out, int out_size) {
    const float* x = (const float*)d_in[0];
    float* out = (float*)d_out;
    const int batch = in_sizes[0] / (NE * DIM);  // 8192
    const int grid = (batch < GRIDSZ) ? batch : GRIDSZ;
    gram_chol_cpasync<<<grid, NT>>>(x, out, batch);
}

// round 13
// speedup vs baseline: 1.1804x; 1.1804x over previous
#include <cuda_runtime.h>

#define NE 8
#define DIM 1024
#define NT 256
#define F4 (DIM / 4)
#define NG 36     // lower triangle of 8x8 Gram
#define RW 129    // 128 partials + 1 pad -> conflict-free column sums

__device__ __forceinline__ constexpr int tri(int i, int j) { return i * (i + 1) / 2 + j; }

__global__ __launch_bounds__(NT, 4) void gram_chol_kernel(
    const float* __restrict__ x, float* __restrict__ out) {
    const int t = threadIdx.x;
    const int warp = t >> 5;
    const int lane = t & 31;

    __shared__ float red[NG][RW];  // 18.6 KB
    __shared__ float gf_s[NG];
    __shared__ float Ls[NG];       // Cholesky factor; diag slots hold 1/L_jj

    const float4* __restrict__ xin =
        reinterpret_cast<const float4*>(x + (size_t)blockIdx.x * NE * DIM);
    float4* __restrict__ xout =
        reinterpret_cast<float4*>(out + (size_t)blockIdx.x * NE * DIM);

    // ---- Load all 8 expert slices (coalesced LDG.128, streaming) ----
    float4 v[NE];
#pragma unroll
    for (int i = 0; i < NE; i++) v[i] = __ldcs(&xin[i * F4 + t]);

    // ---- Gram partials: 1-level shuffle; lanes 0-15 publish 128 partials/value ----
#pragma unroll
    for (int i = 0; i < NE; i++) {
#pragma unroll
        for (int j = 0; j <= i; j++) {
            float s = v[i].x * v[j].x + v[i].y * v[j].y +
                      v[i].z * v[j].z + v[i].w * v[j].w;
            s += __shfl_xor_sync(0xffffffffu, s, 16);
            if (lane < 16) red[tri(i, j)][warp * 16 + lane] = s;
        }
    }
    __syncthreads();

    // ---- Final reduce: threads 0..35 each sum 128 partials (4-way ILP) ----
    if (t < NG) {
        float s0 = 0.f, s1 = 0.f, s2 = 0.f, s3 = 0.f;
#pragma unroll
        for (int m = 0; m < 128; m += 4) {
            s0 += red[t][m + 0];
            s1 += red[t][m + 1];
            s2 += red[t][m + 2];
            s3 += red[t][m + 3];
        }
        gf_s[t] = (s0 + s1) + (s2 + s3);
    }
    __syncthreads();

    // ---- Warp 0: lane-parallel 8x8 Cholesky (lane i owns Gram row i) ----
    if (warp == 0) {
        float grow[NE];  // lane i: G[i][k]; lanes >=8 compute junk harmlessly
        const int li = lane;
#pragma unroll
        for (int k = 0; k < NE; k++) {
            const int r = (li < NE) ? li : 0;
            grow[k] = gf_s[(k <= r) ? tri(r, k) : tri(k, r)];
        }
#pragma unroll
        for (int j = 0; j < NE; j++) {
            const float diag = __shfl_sync(0xffffffffu, grow[j], j);
            const float inv = rsqrtf(diag);
            const float Lij = grow[j] * inv;  // lane i>=j: L[i][j]; lane j: L_jj
            if (li < NE && li >= j) Ls[tri(li, j)] = (li == j) ? inv : Lij;
#pragma unroll
            for (int k = 0; k < NE; k++) {
                if (k > j) {
                    const float Lkj = __shfl_sync(0xffffffffu, Lij, k);
                    grow[k] -= Lij * Lkj;
                }
            }
        }
    }
    __syncthreads();

    // ---- Column-oriented forward substitution: v <- L^-1 v, store as we go ----
#pragma unroll
    for (int j = 0; j < NE; j++) {
        const float invd = Ls[tri(j, j)];  // 1/L_jj (broadcast LDS)
        v[j].x *= invd; v[j].y *= invd; v[j].z *= invd; v[j].w *= invd;
        __stcs(&xout[j * F4 + t], v[j]);
#pragma unroll
        for (int i = 0; i < NE; i++) {
            if (i > j) {
                const float lij = Ls[tri(i, j)];
                v[i].x -= lij * v[j].x;
                v[i].y -= lij * v[j].y;
                v[i].z -= lij * v[j].z;
                v[i].w -= lij * v[j].w;
            }
        }
    }
}

extern "C" void kernel_launch(void* const* d_in, const int* in_sizes, int n_in,
                              void* d_out, int out_size) {
    const float* x = (const float*)d_in[0];
    float* out = (float*)d_out;
    const int batch = in_sizes[0] / (NE * DIM);  // 8192
    gram_chol_kernel<<<batch, NT>>>(x, out);
}

// round 14
// speedup vs baseline: 1.1877x; 1.0062x over previous
#include <cuda_runtime.h>

#define NE 8
#define DIM 1024
#define NT 256
#define F4 (DIM / 4)
#define NG 36     // lower triangle of 8x8 Gram
#define RW 129    // 128 partials + 1 pad -> conflict-free column sums

__device__ __forceinline__ constexpr int tri(int i, int j) { return i * (i + 1) / 2 + j; }

__global__ __launch_bounds__(NT, 4) void gram_chol_kernel(
    const float* __restrict__ x, float* __restrict__ out) {
    const int t = threadIdx.x;
    const int warp = t >> 5;
    const int lane = t & 31;

    __shared__ float red[NG][RW];  // 18.6 KB
    __shared__ float gf_s[NG];
    __shared__ float Ls[NG];       // Cholesky factor; diag slots hold 1/L_jj

    const float4* __restrict__ xin =
        reinterpret_cast<const float4*>(x + (size_t)blockIdx.x * NE * DIM);
    float4* __restrict__ xout =
        reinterpret_cast<float4*>(out + (size_t)blockIdx.x * NE * DIM);

    // ---- Load all 8 expert slices (coalesced LDG.128, streaming) ----
    float4 v[NE];
#pragma unroll
    for (int i = 0; i < NE; i++) v[i] = __ldcs(&xin[i * F4 + t]);

    // ---- Gram partials: 1-level shuffle; lanes 0-15 publish 128 partials/value ----
#pragma unroll
    for (int i = 0; i < NE; i++) {
#pragma unroll
        for (int j = 0; j <= i; j++) {
            float s = v[i].x * v[j].x + v[i].y * v[j].y +
                      v[i].z * v[j].z + v[i].w * v[j].w;
            s += __shfl_xor_sync(0xffffffffu, s, 16);
            if (lane < 16) red[tri(i, j)][warp * 16 + lane] = s;
        }
    }
    __syncthreads();

    // ---- Final reduce: threads 0..35 each sum 128 partials (4-way ILP) ----
    if (t < NG) {
        float s0 = 0.f, s1 = 0.f, s2 = 0.f, s3 = 0.f;
#pragma unroll
        for (int m = 0; m < 128; m += 4) {
            s0 += red[t][m + 0];
            s1 += red[t][m + 1];
            s2 += red[t][m + 2];
            s3 += red[t][m + 3];
        }
        gf_s[t] = (s0 + s1) + (s2 + s3);
    }
    __syncthreads();

    // ---- Warp 0: lane-parallel 8x8 Cholesky (lane i owns Gram row i) ----
    if (warp == 0) {
        float grow[NE];  // lane i: G[i][k]; lanes >=8 compute junk harmlessly
        const int li = lane;
#pragma unroll
        for (int k = 0; k < NE; k++) {
            const int r = (li < NE) ? li : 0;
            grow[k] = gf_s[(k <= r) ? tri(r, k) : tri(k, r)];
        }
#pragma unroll
        for (int j = 0; j < NE; j++) {
            const float diag = __shfl_sync(0xffffffffu, grow[j], j);
            const float inv = rsqrtf(diag);
            const float Lij = grow[j] * inv;  // lane i>=j: L[i][j]; lane j: L_jj
            if (li < NE && li >= j) Ls[tri(li, j)] = (li == j) ? inv : Lij;
#pragma unroll
            for (int k = 0; k < NE; k++) {
                if (k > j) {
                    const float Lkj = __shfl_sync(0xffffffffu, Lij, k);
                    grow[k] -= Lij * Lkj;
                }
            }
        }
    }
    __syncthreads();

    // ---- Column-oriented forward substitution: v <- L^-1 v, store as we go ----
#pragma unroll
    for (int j = 0; j < NE; j++) {
        const float invd = Ls[tri(j, j)];  // 1/L_jj (broadcast LDS)
        v[j].x *= invd; v[j].y *= invd; v[j].z *= invd; v[j].w *= invd;
        __stcs(&xout[j * F4 + t], v[j]);
#pragma unroll
        for (int i = 0; i < NE; i++) {
            if (i > j) {
                const float lij = Ls[tri(i, j)];
                v[i].x -= lij * v[j].x;
                v[i].y -= lij * v[j].y;
                v[i].z -= lij * v[j].z;
                v[i].w -= lij * v[j].w;
            }
        }
    }
}

extern "C" void kernel_launch(void* const* d_in, const int* in_sizes, int n_in,
                              void* d_out, int out_size) {
    const float* x = (const float*)d_in[0];
    float* out = (float*)d_out;
    const int batch = in_sizes[0] / (NE * DIM);  // 8192
    gram_chol_kernel<<<batch, NT>>>(x, out);
}